// round 12
// baseline (speedup 1.0000x reference)
#include <cuda_runtime.h>

// Problem constants (fixed by the dataset)
#define Bc   2
#define Sc   4096
#define Hc   12
#define Gc   64
#define Wc   513
#define WGc  577      // G + W
#define HALF 256      // W/2
#define BSc  (Bc * Sc)

#define N_SPLIT         16           // s-splits per 128-wide i-tile
#define N_TILES         (Bc * 32)    // 128-wide i-tiles
#define N_LOCAL_BLOCKS  (N_TILES * N_SPLIT)   // 1024
#define N_GCHUNK        96           // row-chunks per batch for global sums
#define N_GLOBAL_BLOCKS (Bc * N_GCHUNK)       // 192
#define N_BLOCKS        (N_LOCAL_BLOCKS + N_GLOBAL_BLOCKS)   // 1216 = 8*152

// Scratch. Zero at module load (.bss); the last block consumes AND re-zeroes
// everything, so every launch/replay sees zeros. Allocation-free.
__device__ float        g_probs_sum[BSc];   // accumulated local sums
__device__ float        g_gs[Bc * Gc];      // accumulated global sums
__device__ unsigned int g_done;             // completed-block counter

// ---------------------------------------------------------------------------
// Single fused kernel: 227 MB streamed once (DRAM-bound), finalize done
// inline by the last block to finish (no second graph node).
//
// Local role (blocks 0..1023): local_sum[b,i] = sum_{s,h} probs[b,s,h,320+i-s]
//   Block owns 128 consecutive i -> contiguous 512B spans per (s,h).
// Global role (blocks 1024..1215): global_sum[b,c] = sum_{s,h} probs[b,s,h,c]
// Last block: scatter + per-batch max + threshold + outputs + scratch zero.
// ---------------------------------------------------------------------------
__global__ __launch_bounds__(256, 8) void main_kernel(
    const float* __restrict__ probs, const float* __restrict__ mask,
    const float* __restrict__ thr_p,
    const void* __restrict__ lbv, const void* __restrict__ liv,
    const void* __restrict__ gbv, const void* __restrict__ giv,
    int n, float* __restrict__ out)
{
    // One buffer, reused: role-phase reduction scratch, then finalize ps/gs.
    __shared__ float sbuf[Sc + 192];          // 16.75 KB -> 8 blocks/SM OK
    __shared__ unsigned int s_last;
    __shared__ int   is32;
    __shared__ float s_pm;

    const int tid = threadIdx.x;

    if (blockIdx.x < N_LOCAL_BLOCKS) {
        const int tile  = blockIdx.x >> 4;    // 0..63
        const int split = blockIdx.x & 15;    // 0..15
        const int w     = tid >> 5;           // 0..7
        const int lane  = tid & 31;
        const int iw    = w & 3;              // i-subtile within block
        const int sg    = w >> 2;             // s-subgroup (0,1)

        const int b  = tile >> 5;             // 32 tiles per batch
        const int i0 = (tile & 31) << 7;      // i base (128-wide tile)
        const int i  = i0 + iw * 32 + lane;   // this thread's output token

        // s-window for this tile: [i0-256, i0+384), 640 values = 16*2*20
        const int s_start = i0 - HALF + split * 40 + sg * 20;

        const float* __restrict__ mrow = mask + b * Sc;
        float acc = 0.0f;

        #pragma unroll 1
        for (int t = 0; t < 20; ++t) {
            const int s = s_start + t;
            if (s < 0 || s >= Sc) continue;
            const int c = Gc + HALF + i - s;           // column for this i
            if (c < Gc || c >= WGc) continue;          // diagonal band edges
            const float flag = (mrow[s] >= 0.0f) ? 1.0f : 0.0f;
            const float* __restrict__ row =
                probs + (size_t)(b * Sc + s) * Hc * WGc + c;
            float a = 0.0f;
            #pragma unroll
            for (int h = 0; h < Hc; ++h)               // 12 independent loads
                a += row[(size_t)h * WGc];
            acc += flag * a;
        }

        float* red = sbuf;                    // [2][4][33] = 264 floats
        red[(sg * 4 + iw) * 33 + lane] = acc;
        __syncthreads();
        if (sg == 0)                          // warps 0..3 emit one atomic each
            atomicAdd(&g_probs_sum[b * Sc + i],
                      red[iw * 33 + lane] + red[(4 + iw) * 33 + lane]);
    } else {
        const int idx   = blockIdx.x - N_LOCAL_BLOCKS;  // 0..191
        const int b     = idx / N_GCHUNK;
        const int chunk = idx % N_GCHUNK;
        const int c     = tid & 63;
        const int rg    = tid >> 6;

        const float* __restrict__ mrow = mask + b * Sc;
        const float* __restrict__ base = probs + (size_t)b * Sc * Hc * WGc;

        float acc = 0.0f;
        const int r0 = chunk * 512;      // rows are (s*H + h), 49152 per batch
        #pragma unroll 8
        for (int r = r0 + rg; r < r0 + 512; r += 4) {
            const int s = r / Hc;
            const float flag = (mrow[s] >= 0.0f) ? 1.0f : 0.0f;
            acc += flag * base[(size_t)r * WGc + c];
        }

        float* gred = sbuf;                   // [4][64]
        gred[rg * 64 + c] = acc;
        __syncthreads();
        if (rg == 0)
            atomicAdd(&g_gs[b * Gc + c],
                      gred[c] + gred[64 + c] + gred[128 + c] + gred[192 + c]);
    }

    // ---- completion counter: last block runs the finalize ----
    __threadfence();                          // make our atomics globally visible
    __syncthreads();
    if (tid == 0) {
        const unsigned int old = atomicAdd(&g_done, 1u);
        s_last = (old == N_BLOCKS - 1) ? 1u : 0u;
    }
    __syncthreads();
    if (!s_last) return;

    // =================== FINALIZE (one 256-thread block) ===================
    __threadfence();                          // acquire: see all blocks' sums
    float* ps   = sbuf;                       // 4096 floats (one batch)
    float* gs   = sbuf + Sc;                  // 128 floats
    float* smax = sbuf + Sc + 128;            // 8 floats (per-warp maxima)
    const int lane = tid & 31, wrp = tid >> 5;

    if (tid < Bc * Gc) { gs[tid] = g_gs[tid]; g_gs[tid] = 0.0f; }
    if (tid == 0) { is32 = 0; g_done = 0u; }
    __syncthreads();

    // dtype detect on glob_i: int32 data viewed as int64 words yields values
    // outside [0, 2^31). Scan n/2 words (safe in either layout).
    if (tid < n / 2) {
        const long long v = ((const long long*)giv)[tid];
        if (v < 0 || v >= (1LL << 31)) atomicOr(&is32, 1);
    }
    __syncthreads();

    const float thr = fmaxf(1e-5f, thr_p[0]);

    for (int b = 0; b < Bc; ++b) {
        // pull this batch's sums into smem, zero the global copy
        #pragma unroll
        for (int k = 0; k < 4; ++k) {
            const int idx = tid + k * 256;    // float4 slot, 0..1023
            ((float4*)ps)[idx] = ((const float4*)(g_probs_sum + b * Sc))[idx];
            ((float4*)(g_probs_sum + b * Sc))[idx] =
                make_float4(0.f, 0.f, 0.f, 0.f);
        }
        __syncthreads();

        // scatter: probs_sum[lb, li] += global_sum[gb, gi] (duplicates add)
        for (int k = tid; k < n; k += 256) {
            int lb, li, gb, gi;
            if (is32) {
                lb = ((const int*)lbv)[k];
                li = ((const int*)liv)[k];
                gb = ((const int*)gbv)[k];
                gi = ((const int*)giv)[k];
            } else {
                lb = (int)((const long long*)lbv)[k];
                li = (int)((const long long*)liv)[k];
                gb = (int)((const long long*)gbv)[k];
                gi = (int)((const long long*)giv)[k];
            }
            if (lb == b) atomicAdd(&ps[li], gs[gb * Gc + gi]);
        }
        __syncthreads();

        // per-batch max: 16 values/thread -> warp shuffle -> cross-warp
        float m = -1e30f;
        float4 v[4];
        #pragma unroll
        for (int k = 0; k < 4; ++k) {
            v[k] = ((const float4*)ps)[tid + k * 256];
            m = fmaxf(m, fmaxf(fmaxf(v[k].x, v[k].y), fmaxf(v[k].z, v[k].w)));
        }
        #pragma unroll
        for (int off = 16; off >= 1; off >>= 1)
            m = fmaxf(m, __shfl_xor_sync(0xffffffffu, m, off));
        if (lane == 0) smax[wrp] = m;
        __syncthreads();
        if (wrp == 0) {
            float mm = (lane < 8) ? smax[lane] : -1e30f;
            #pragma unroll
            for (int off = 16; off >= 1; off >>= 1)
                mm = fmaxf(mm, __shfl_xor_sync(0xffffffffu, mm, off));
            if (lane == 0) s_pm = mm;
        }
        __syncthreads();
        const float pm = s_pm;

        // outputs: [ new_attention_mask (B*S) | scores (B*S) ]
        #pragma unroll
        for (int k = 0; k < 4; ++k) {
            const int idx = tid + k * 256;
            const float4 sc = make_float4(v[k].x / pm, v[k].y / pm,
                                          v[k].z / pm, v[k].w / pm);
            float4 mk;
            mk.x = (sc.x < thr) ? -10000.0f : 0.0f;
            mk.y = (sc.y < thr) ? -10000.0f : 0.0f;
            mk.z = (sc.z < thr) ? -10000.0f : 0.0f;
            mk.w = (sc.w < thr) ? -10000.0f : 0.0f;
            ((float4*)(out + b * Sc))[idx]       = mk;
            ((float4*)(out + BSc + b * Sc))[idx] = sc;
        }
        __syncthreads();
    }
}

// ---------------------------------------------------------------------------
// launch — ONE graph node, allocation-free.
// Inputs (metadata order): attention_mask f32, attention_probs f32,
// keep_threshold f32[1], max_num_global_attn_indices (unused),
// loc_b, loc_i, glob_b, glob_i.
// ---------------------------------------------------------------------------
extern "C" void kernel_launch(void* const* d_in, const int* in_sizes, int n_in,
                              void* d_out, int out_size)
{
    const float* mask  = (const float*)d_in[0];
    const float* probs = (const float*)d_in[1];
    const float* thr   = (const float*)d_in[2];
    const void*  lb    = d_in[4];
    const void*  li    = d_in[5];
    const void*  gb    = d_in[6];
    const void*  gi    = d_in[7];
    float* out = (float*)d_out;
    const int n_idx = in_sizes[4];

    main_kernel<<<N_BLOCKS, 256>>>(probs, mask, thr, lb, li, gb, gi,
                                   n_idx, out);
}